// round 3
// baseline (speedup 1.0000x reference)
#include <cuda_runtime.h>
#include <cstdint>

// EntailmentConeLoss: loss = 0.5*( mean_i E(p_i,cpos_i) + mean_{i,k} relu(MARGIN - E(p_i,cneg_{ik})) )
// E(p,c) = relu(acos(clip((|c|^2-|p|^2-|c-p|^2)/(2|p||c-p|+eps))) - asin(clip(BETA/(|p|+eps),0,1-eps)))

#define C_CONST 100000
#define D_CONST 256
#define P_CONST 65536
#define K_CONST 4
#define BETA 0.1f
#define MARGIN 0.1f
#define EPS 1e-6f

#define WARPS_PER_BLOCK 8
#define THREADS_PER_BLOCK (WARPS_PER_BLOCK * 32)
#define NUM_BLOCKS (P_CONST / WARPS_PER_BLOCK)   // 8192
#define NROWS 5                                   // 1 pos + 4 neg c-rows per pair

__device__ float        g_partials[NUM_BLOCKS];
__device__ unsigned int g_count;   // zero-init; last block resets to 0 each call (graph-replay safe)

__device__ __forceinline__ float warp_sum(float v) {
    #pragma unroll
    for (int o = 16; o > 0; o >>= 1) v += __shfl_xor_sync(0xFFFFFFFFu, v, o);
    return v;
}

__global__ __launch_bounds__(THREADS_PER_BLOCK)
void cone_loss_kernel(const float* __restrict__ protos,
                      const int*   __restrict__ pairs,
                      const int*   __restrict__ neg_c,
                      float*       __restrict__ out) {
    const int wid  = threadIdx.x >> 5;
    const int lane = threadIdx.x & 31;
    const int pair = blockIdx.x * WARPS_PER_BLOCK + wid;   // one warp per pair

    __shared__ float s_warp[WARPS_PER_BLOCK];

    // ---- gather all indices up front ----
    const int  p_idx = pairs[2 * pair + 0];
    const int  c_idx = pairs[2 * pair + 1];
    const int4 nidx  = __ldg(reinterpret_cast<const int4*>(neg_c) + pair); // 16B-aligned: 4 negatives
    int rows[NROWS] = { c_idx, nidx.x, nidx.y, nidx.z, nidx.w };

    // ---- load p row (256 floats): 2x float4 per lane ----
    const float4* pbase = reinterpret_cast<const float4*>(protos);
    const float4* prow  = pbase + (size_t)p_idx * (D_CONST / 4);
    float4 pa = __ldg(&prow[lane]);
    float4 pb = __ldg(&prow[lane + 32]);

    float sp2_part = pa.x*pa.x + pa.y*pa.y + pa.z*pa.z + pa.w*pa.w
                   + pb.x*pb.x + pb.y*pb.y + pb.z*pb.z + pb.w*pb.w;

    // ---- PHASE 1: per-lane partials for all 5 c-rows, NO shfls in between ----
    // All 10 LDG.128 issue with high MLP; compiler hoists loads across rows.
    float cc[NROWS], sd[NROWS];
    #pragma unroll
    for (int r = 0; r < NROWS; r++) {
        const float4* crow = pbase + (size_t)rows[r] * (D_CONST / 4);
        float4 ca = __ldg(&crow[lane]);
        float4 cb = __ldg(&crow[lane + 32]);
        cc[r] = ca.x*ca.x + ca.y*ca.y + ca.z*ca.z + ca.w*ca.w
              + cb.x*cb.x + cb.y*cb.y + cb.z*cb.z + cb.w*cb.w;
        float dax = ca.x - pa.x, day = ca.y - pa.y, daz = ca.z - pa.z, daw = ca.w - pa.w;
        float dbx = cb.x - pb.x, dby = cb.y - pb.y, dbz = cb.z - pb.z, dbw = cb.w - pb.w;
        sd[r] = dax*dax + day*day + daz*daz + daw*daw
              + dbx*dbx + dby*dby + dbz*dbz + dbw*dbw;
    }

    // ---- PHASE 2: 11 interleaved butterfly reductions (5 dep stages, 11-wide ILP) ----
    #pragma unroll
    for (int o = 16; o > 0; o >>= 1) {
        sp2_part += __shfl_xor_sync(0xFFFFFFFFu, sp2_part, o);
        #pragma unroll
        for (int r = 0; r < NROWS; r++) {
            cc[r] += __shfl_xor_sync(0xFFFFFFFFu, cc[r], o);
            sd[r] += __shfl_xor_sync(0xFFFFFFFFu, sd[r], o);
        }
    }
    const float sp2    = sp2_part;
    const float norm_p = sqrtf(sp2);

    // aperture depends on p only
    float sa = BETA / (norm_p + EPS);
    sa = fminf(fmaxf(sa, 0.0f), 1.0f - EPS);
    const float aperture = asinf(sa);

    // ---- energies (computed redundantly on all lanes; cheap) ----
    float e[NROWS];
    #pragma unroll
    for (int r = 0; r < NROWS; r++) {
        float sd2 = fmaxf(sd[r], 0.0f);
        float num   = cc[r] - sp2 - sd2;
        float denom = 2.0f * norm_p * sqrtf(sd2) + EPS;
        float cosang = num / denom;
        cosang = fminf(fmaxf(cosang, -1.0f + EPS), 1.0f - EPS);
        e[r] = fmaxf(acosf(cosang) - aperture, 0.0f);
    }

    float neg_sum = fmaxf(MARGIN - e[1], 0.0f) + fmaxf(MARGIN - e[2], 0.0f)
                  + fmaxf(MARGIN - e[3], 0.0f) + fmaxf(MARGIN - e[4], 0.0f);

    if (lane == 0) {
        s_warp[wid] = 0.5f * (e[0]    * (1.0f / (float)P_CONST)
                            + neg_sum * (1.0f / ((float)P_CONST * (float)K_CONST)));
    }
    __syncthreads();

    if (threadIdx.x == 0) {
        float acc = 0.0f;
        #pragma unroll
        for (int w = 0; w < WARPS_PER_BLOCK; w++) acc += s_warp[w];
        g_partials[blockIdx.x] = acc;
    }

    // ---- last-block final reduction (threadfence + counter pattern) ----
    __shared__ bool is_last;
    __threadfence();
    if (threadIdx.x == 0) {
        unsigned int t = atomicAdd(&g_count, 1u);
        is_last = (t == (unsigned int)(gridDim.x - 1));
    }
    __syncthreads();

    if (is_last) {
        float acc = 0.0f;
        for (int j = threadIdx.x; j < NUM_BLOCKS; j += THREADS_PER_BLOCK)
            acc += g_partials[j];
        acc = warp_sum(acc);
        if (lane == 0) s_warp[wid] = acc;
        __syncthreads();
        if (threadIdx.x == 0) {
            float tot = 0.0f;
            #pragma unroll
            for (int w = 0; w < WARPS_PER_BLOCK; w++) tot += s_warp[w];
            out[0]  = tot;
            g_count = 0;   // reset for next graph replay
        }
    }
}

extern "C" void kernel_launch(void* const* d_in, const int* in_sizes, int n_in,
                              void* d_out, int out_size) {
    const float* protos = (const float*)d_in[0];
    const int*   pairs  = (const int*)d_in[1];
    const int*   negc   = (const int*)d_in[2];
    float* out = (float*)d_out;

    cone_loss_kernel<<<NUM_BLOCKS, THREADS_PER_BLOCK>>>(protos, pairs, negc, out);
}

// round 4
// speedup vs baseline: 1.1531x; 1.1531x over previous
#include <cuda_runtime.h>
#include <cstdint>

// EntailmentConeLoss: loss = 0.5*( mean_i E(p_i,cpos_i) + mean_{i,k} relu(MARGIN - E(p_i,cneg_{ik})) )
// E(p,c) = relu(acos(clip(num/denom)) - asin(clip(BETA/(|p|+eps),0,1-eps)))
// Reformulated: dot = <p,c>;  num = 2*(dot - |p|^2);  |c-p|^2 = |c|^2 + |p|^2 - 2*dot

#define C_CONST 100000
#define D_CONST 256
#define P_CONST 65536
#define K_CONST 4
#define BETA 0.1f
#define MARGIN 0.1f
#define EPS 1e-6f

#define WARPS_PER_BLOCK 8
#define THREADS_PER_BLOCK (WARPS_PER_BLOCK * 32)
#define NUM_BLOCKS (P_CONST / WARPS_PER_BLOCK)   // 8192

__device__ __align__(16) float g_partials[NUM_BLOCKS];

__device__ __forceinline__ float warp_sum(float v) {
    #pragma unroll
    for (int o = 16; o > 0; o >>= 1) v += __shfl_xor_sync(0xFFFFFFFFu, v, o);
    return v;
}

__global__ __launch_bounds__(THREADS_PER_BLOCK, 7)
void cone_loss_kernel(const float* __restrict__ protos,
                      const int*   __restrict__ pairs,
                      const int*   __restrict__ neg_c) {
    const int wid  = threadIdx.x >> 5;
    const int lane = threadIdx.x & 31;
    const int pair = blockIdx.x * WARPS_PER_BLOCK + wid;   // one warp per pair

    __shared__ float s_warp[WARPS_PER_BLOCK];

    // ---- indices ----
    const int  p_idx = pairs[2 * pair + 0];
    const int  c_idx = pairs[2 * pair + 1];
    const int4 nidx  = __ldg(reinterpret_cast<const int4*>(neg_c) + pair);

    // ---- load p row (256 floats): 2x float4 per lane ----
    const float4* pbase = reinterpret_cast<const float4*>(protos);
    const float4* prow  = pbase + (size_t)p_idx * (D_CONST / 4);
    const float4 pa = __ldg(&prow[lane]);
    const float4 pb = __ldg(&prow[lane + 32]);

    float sp2 = warp_sum(pa.x*pa.x + pa.y*pa.y + pa.z*pa.z + pa.w*pa.w
                       + pb.x*pb.x + pb.y*pb.y + pb.z*pb.z + pb.w*pb.w);
    const float norm_p = sqrtf(sp2);

    // aperture: asin(sa) with sa ~ 0.006 -> cubic Taylor, |err| < 1e-11
    float sa = BETA / (norm_p + EPS);
    sa = fminf(fmaxf(sa, 0.0f), 1.0f - EPS);
    const float aperture = sa * (1.0f + sa * sa * (1.0f / 6.0f));

    // ---- serial per-row processing (dot formulation) ----
    float e_pos = 0.0f, neg_sum = 0.0f;
    #pragma unroll
    for (int r = 0; r < 5; r++) {
        int cidx = (r == 0) ? c_idx : ((r == 1) ? nidx.x : (r == 2) ? nidx.y
                                      : (r == 3) ? nidx.z : nidx.w);
        const float4* crow = pbase + (size_t)cidx * (D_CONST / 4);
        float4 ca = __ldg(&crow[lane]);
        float4 cb = __ldg(&crow[lane + 32]);

        float cc_p  = ca.x*ca.x + ca.y*ca.y + ca.z*ca.z + ca.w*ca.w
                    + cb.x*cb.x + cb.y*cb.y + cb.z*cb.z + cb.w*cb.w;
        float dot_p = ca.x*pa.x + ca.y*pa.y + ca.z*pa.z + ca.w*pa.w
                    + cb.x*pb.x + cb.y*pb.y + cb.z*pb.z + cb.w*pb.w;

        // two interleaved butterfly reductions (5 dependent stages, 2-wide ILP)
        #pragma unroll
        for (int o = 16; o > 0; o >>= 1) {
            cc_p  += __shfl_xor_sync(0xFFFFFFFFu, cc_p,  o);
            dot_p += __shfl_xor_sync(0xFFFFFFFFu, dot_p, o);
        }

        float sd2 = fmaxf(cc_p + sp2 - 2.0f * dot_p, 0.0f);
        float num = 2.0f * (dot_p - sp2);
        float denom = 2.0f * norm_p * sqrtf(sd2) + EPS;
        float cosang = num / denom;
        cosang = fminf(fmaxf(cosang, -1.0f + EPS), 1.0f - EPS);
        float e = fmaxf(acosf(cosang) - aperture, 0.0f);

        if (r == 0) e_pos = e;
        else        neg_sum += fmaxf(MARGIN - e, 0.0f);
    }

    if (lane == 0) {
        s_warp[wid] = 0.5f * (e_pos   * (1.0f / (float)P_CONST)
                            + neg_sum * (1.0f / ((float)P_CONST * (float)K_CONST)));
    }
    __syncthreads();

    if (threadIdx.x == 0) {
        float acc = 0.0f;
        #pragma unroll
        for (int w = 0; w < WARPS_PER_BLOCK; w++) acc += s_warp[w];
        g_partials[blockIdx.x] = acc;
    }
}

__global__ __launch_bounds__(1024)
void reduce_kernel(float* __restrict__ out) {
    __shared__ float s[32];
    const int tid = threadIdx.x;
    // 8192 floats = 2048 float4; 1024 threads x 2 float4 each
    const float4* src = reinterpret_cast<const float4*>(g_partials);
    float4 a = __ldg(&src[tid]);
    float4 b = __ldg(&src[tid + 1024]);
    float acc = a.x + a.y + a.z + a.w + b.x + b.y + b.z + b.w;
    acc = warp_sum(acc);
    if ((tid & 31) == 0) s[tid >> 5] = acc;
    __syncthreads();
    if (tid < 32) {
        float v = s[tid];
        v = warp_sum(v);
        if (tid == 0) out[0] = v;
    }
}

extern "C" void kernel_launch(void* const* d_in, const int* in_sizes, int n_in,
                              void* d_out, int out_size) {
    const float* protos = (const float*)d_in[0];
    const int*   pairs  = (const int*)d_in[1];
    const int*   negc   = (const int*)d_in[2];
    float* out = (float*)d_out;

    cone_loss_kernel<<<NUM_BLOCKS, THREADS_PER_BLOCK>>>(protos, pairs, negc);
    reduce_kernel<<<1, 1024>>>(out);
}